// round 6
// baseline (speedup 1.0000x reference)
#include <cuda_runtime.h>
#include <math.h>

#define DEG   16
#define D     64
#define D2    128
#define BQ    1024
#define NQ    2058
#define WPAD  132          /* padded W1 row stride (words); 528B = 16B multiple */
#define GRID  1029         /* 2 queries per block, exact */

// ---------------------------------------------------------------------------
__global__ __launch_bounds__(256)
void k_fused(const float* __restrict__ feat,
             const int*   __restrict__ adj,
             const int*   __restrict__ in1,
             const int*   __restrict__ in2,
             const int*   __restrict__ neg,
             const float* __restrict__ W1,
             const float* __restrict__ b1,
             const float* __restrict__ W2,
             const float* __restrict__ b2,
             float*       __restrict__ out) {
    __shared__ __align__(16) float W1s[D][WPAD];    // 33 KB, natural row layout
    __shared__ __align__(16) float xq[4][2 * D][4]; // [group][dim][slot]  8 KB
    __shared__ __align__(16) float part[4][D];      // group-partial tanh sums
    __shared__ __align__(16) float x2s[2 * D];      // hop-2 input
    __shared__ __align__(16) float yp[2][D2];       // hop-2 half partials
    __shared__ float b1s[D];
    __shared__ float red[4];

    int tid = threadIdx.x;

    // stage W1 (coalesced float4), once per block
    #pragma unroll
    for (int r = 0; r < 8; ++r) {
        int e = r * 256 + tid;                   // float4 index into W1
        float4 v = ((const float4*)W1)[e];
        int idx = e * 4;
        *(float4*)&W1s[idx >> 7][idx & 127] = v;
    }
    if (tid < D) b1s[tid] = b1[tid];

    int g    = tid >> 6;     // group 0..3
    int j    = tid & 63;     // hop-1 output column
    int col  = tid & 127;    // hop-2 output column
    int half = tid >> 7;     // hop-2 i-range half

    for (int q = blockIdx.x; q < NQ; q += GRID) {
        int qn = (q < BQ) ? in1[q] : (q < 2 * BQ) ? in2[q - BQ] : neg[q - 2 * BQ];

        // ---------------- gather phase --------------------------------
        if (tid < D) x2s[tid] = feat[qn * D + tid];   // self features

        int4 nn4 = *(const int4*)(adj + qn * DEG + g * 4);
        int nodes[4] = {nn4.x, nn4.y, nn4.z, nn4.w};
        #pragma unroll 2
        for (int s = 0; s < 4; ++s) {
            int node = nodes[s];
            float self = feat[node * D + j];
            const int4* a4 = (const int4*)(adj + node * DEG);
            int4 a0 = a4[0], a1 = a4[1], a2 = a4[2], a3 = a4[3];
            float t0 = feat[a0.x * D + j] + feat[a0.y * D + j]
                     + feat[a0.z * D + j] + feat[a0.w * D + j];
            float t1 = feat[a1.x * D + j] + feat[a1.y * D + j]
                     + feat[a1.z * D + j] + feat[a1.w * D + j];
            float t2 = feat[a2.x * D + j] + feat[a2.y * D + j]
                     + feat[a2.z * D + j] + feat[a2.w * D + j];
            float t3 = feat[a3.x * D + j] + feat[a3.y * D + j]
                     + feat[a3.z * D + j] + feat[a3.w * D + j];
            xq[g][j][s]     = self;
            xq[g][D + j][s] = (t0 + t1) + (t2 + t3);
        }
        __syncthreads();                              // A

        // ---------------- hop-1 GEMV (scalar FFMA) + tanh -------------
        {
            float bb = b1s[j];
            float a0 = bb, a1 = bb, a2 = bb, a3 = bb;
            #pragma unroll 8
            for (int i4 = 0; i4 < (2 * D) / 4; ++i4) {
                float4 w4 = *(const float4*)&W1s[j][i4 * 4];
                #pragma unroll
                for (int e = 0; e < 4; ++e) {
                    float we = (e == 0) ? w4.x : (e == 1) ? w4.y
                             : (e == 2) ? w4.z : w4.w;
                    float4 xv = *(const float4*)&xq[g][i4 * 4 + e][0]; // warp bcast
                    a0 += we * xv.x; a1 += we * xv.y;
                    a2 += we * xv.z; a3 += we * xv.w;
                }
            }
            part[g][j] = (tanhf(a0) + tanhf(a1)) + (tanhf(a2) + tanhf(a3));
        }
        __syncthreads();                              // B

        if (tid < D)
            x2s[D + tid] = (part[0][tid] + part[1][tid])
                         + (part[2][tid] + part[3][tid]);
        __syncthreads();                              // C

        // ---------------- hop-2 GEMV (split over 2 halves) ------------
        {
            const float4* w2r = (const float4*)(W2 + col * (2 * D) + half * D);
            const float*  xh  = x2s + half * D;
            float acc = 0.f;
            #pragma unroll 8
            for (int i4 = 0; i4 < D / 4; ++i4) {
                float4 w = w2r[i4];
                acc += w.x * xh[i4 * 4 + 0] + w.y * xh[i4 * 4 + 1]
                     + w.z * xh[i4 * 4 + 2] + w.w * xh[i4 * 4 + 3];
            }
            yp[half][col] = acc;
        }
        __syncthreads();                              // D

        float y = 0.f;
        if (tid < D2) {
            y = yp[0][tid] + yp[1][tid] + b2[tid];
            float sq = y * y;
            #pragma unroll
            for (int off = 16; off; off >>= 1)
                sq += __shfl_xor_sync(0xffffffffu, sq, off);
            if ((tid & 31) == 0) red[tid >> 5] = sq;
        }
        __syncthreads();                              // E

        if (tid < D2) {
            float tot = (red[0] + red[1]) + (red[2] + red[3]);
            out[q * D2 + tid] = y / fmaxf(sqrtf(tot), 1e-12f);
        }
        __syncthreads();                              // F
    }
}

// ---------------------------------------------------------------------------
extern "C" void kernel_launch(void* const* d_in, const int* in_sizes, int n_in,
                              void* d_out, int out_size) {
    const float* feat = (const float*)d_in[0];   // [65536, 64]
    const int*   adj  = (const int*)  d_in[1];   // [65536, 16]
    const int*   in1  = (const int*)  d_in[2];   // [1024]
    const int*   in2  = (const int*)  d_in[3];   // [1024]
    const int*   neg  = (const int*)  d_in[4];   // [10]
    const float* W1   = (const float*)d_in[5];   // [64, 128]
    const float* b1   = (const float*)d_in[6];   // [64]
    const float* W2   = (const float*)d_in[7];   // [128, 128]
    const float* b2   = (const float*)d_in[8];   // [128]
    float*       out  = (float*)d_out;           // [2058, 128]

    k_fused<<<GRID, 256>>>(feat, adj, in1, in2, neg, W1, b1, W2, b2, out);
}